// round 7
// baseline (speedup 1.0000x reference)
#include <cuda_runtime.h>
#include <cuda_bf16.h>
#include <cuda_fp16.h>
#include <cstdint>

#define SQ 4096
#define DM 1024
#define NH 16
#define HS 64
#define QSCALE 0.125f
#define LOG2E 1.4426950408889634f
#define NEG -1e9f

// -------- scratch (no allocations allowed) --------
__device__ __align__(16) __nv_bfloat16 g_xhi[SQ * DM];
__device__ __align__(16) __nv_bfloat16 g_xlo[SQ * DM];
__device__ __align__(16) __nv_bfloat16 g_whi[4 * DM * DM];
__device__ __align__(16) __nv_bfloat16 g_wlo[4 * DM * DM];
__device__ __align__(16) __nv_bfloat16 g_qhi[NH * SQ * HS];
__device__ __align__(16) __nv_bfloat16 g_qlo[NH * SQ * HS];
__device__ __align__(16) __nv_bfloat16 g_khi[NH * SQ * HS];
__device__ __align__(16) __nv_bfloat16 g_klo[NH * SQ * HS];
__device__ __align__(16) __half       g_vhi[NH * SQ * HS];

// ============================================================================
// helpers
// ============================================================================
__device__ __forceinline__ uint32_t smem_u32(const void* p) {
    uint32_t a;
    asm("{ .reg .u64 t; cvta.to.shared.u64 t, %1; cvt.u32.u64 %0, t; }" : "=r"(a) : "l"(p));
    return a;
}

#define LDSM_X4(r0, r1, r2, r3, addr) \
    asm volatile("ldmatrix.sync.aligned.m8n8.x4.shared.b16 {%0,%1,%2,%3}, [%4];" \
                 : "=r"(r0), "=r"(r1), "=r"(r2), "=r"(r3) : "r"(addr))

#define LDSM_X4_T(r0, r1, r2, r3, addr) \
    asm volatile("ldmatrix.sync.aligned.m8n8.x4.trans.shared.b16 {%0,%1,%2,%3}, [%4];" \
                 : "=r"(r0), "=r"(r1), "=r"(r2), "=r"(r3) : "r"(addr))

__device__ __forceinline__ void mma_bf16(float4& d, const uint32_t* a, uint32_t b0, uint32_t b1) {
    asm volatile("mma.sync.aligned.m16n8k16.row.col.f32.bf16.bf16.f32 "
                 "{%0,%1,%2,%3}, {%4,%5,%6,%7}, {%8,%9}, {%0,%1,%2,%3};"
                 : "+f"(d.x), "+f"(d.y), "+f"(d.z), "+f"(d.w)
                 : "r"(a[0]), "r"(a[1]), "r"(a[2]), "r"(a[3]), "r"(b0), "r"(b1));
}

__device__ __forceinline__ void mma_f16(float4& d, const uint32_t* a, uint32_t b0, uint32_t b1) {
    asm volatile("mma.sync.aligned.m16n8k16.row.col.f32.f16.f16.f32 "
                 "{%0,%1,%2,%3}, {%4,%5,%6,%7}, {%8,%9}, {%0,%1,%2,%3};"
                 : "+f"(d.x), "+f"(d.y), "+f"(d.z), "+f"(d.w)
                 : "r"(a[0]), "r"(a[1]), "r"(a[2]), "r"(a[3]), "r"(b0), "r"(b1));
}

__device__ __forceinline__ void cp16(uint32_t s, const void* g) {
    asm volatile("cp.async.cg.shared.global [%0], [%1], 16;" :: "r"(s), "l"(g));
}
__device__ __forceinline__ void cp_commit() {
    asm volatile("cp.async.commit_group;" ::: "memory");
}
template <int N>
__device__ __forceinline__ void cp_wait() {
    asm volatile("cp.async.wait_group %0;" :: "n"(N) : "memory");
}

__device__ __forceinline__ unsigned pack_bf2(float a, float b) {
    __nv_bfloat16 ha = __float2bfloat16_rn(a);
    __nv_bfloat16 hb = __float2bfloat16_rn(b);
    return (unsigned)__bfloat16_as_ushort(ha) | ((unsigned)__bfloat16_as_ushort(hb) << 16);
}
__device__ __forceinline__ unsigned pack_hi2(float a, float b, unsigned& lo) {
    __nv_bfloat16 ha = __float2bfloat16_rn(a);
    __nv_bfloat16 hb = __float2bfloat16_rn(b);
    float ra = a - __bfloat162float(ha);
    float rb = b - __bfloat162float(hb);
    lo = pack_bf2(ra, rb);
    return (unsigned)__bfloat16_as_ushort(ha) | ((unsigned)__bfloat16_as_ushort(hb) << 16);
}
__device__ __forceinline__ unsigned pack_h2(float a, float b) {
    __half2 h = __floats2half2_rn(a, b);
    return *(unsigned*)&h;
}

// ============================================================================
// fused split: z<4 -> weights into g_whi/g_wlo, z==4 -> x into g_xhi/g_xlo
// ============================================================================
__global__ __launch_bounds__(256)
void split5_kernel(const float4* __restrict__ w0, const float4* __restrict__ w1,
                   const float4* __restrict__ w2, const float4* __restrict__ w3,
                   const float4* __restrict__ x)
{
    const int z = blockIdx.z;
    const float4* src;
    uint2 *hi, *lo;
    int n4;
    if (z < 4) {
        src = (z == 0) ? w0 : (z == 1) ? w1 : (z == 2) ? w2 : w3;
        hi = (uint2*)(g_whi + (size_t)z * DM * DM);
        lo = (uint2*)(g_wlo + (size_t)z * DM * DM);
        n4 = DM * DM / 4;
    } else {
        src = x;
        hi = (uint2*)g_xhi;
        lo = (uint2*)g_xlo;
        n4 = SQ * DM / 4;
    }
    for (int i = blockIdx.x * blockDim.x + threadIdx.x; i < n4;
         i += gridDim.x * blockDim.x) {
        float4 v = src[i];
        unsigned l0, l1;
        unsigned h0 = pack_hi2(v.x, v.y, l0);
        unsigned h1 = pack_hi2(v.z, v.w, l1);
        hi[i] = make_uint2(h0, h1);
        lo[i] = make_uint2(l0, l1);
    }
}

// ============================================================================
// GEMM via mma.sync: out = A[M,K] @ W[N,K]^T + bias.  bf16 hi/lo 3-term.
// 128x128 tile, K-chunk 32, 2-stage cp.async pipeline, row stride 80B.
// MODE 0: QKV epilogue (split q/k bf16 + v fp16, q pre-scaled into exp2 domain)
// MODE 1: O epilogue (fp32 + bias)
// ============================================================================
#define GRS 80                 // gemm smem row stride bytes (32 bf16 + 16B pad)
#define G_STG 40960            // bytes per pipeline stage (4 arrays * 128 * 80)
#define GA_HI 0
#define GA_LO 10240
#define GB_HI 20480
#define GB_LO 30720

template <int MODE>
__global__ __launch_bounds__(256, 2)
void gemm_mma(const __nv_bfloat16* __restrict__ Ahi,
              const __nv_bfloat16* __restrict__ Alo,
              int wslot,
              const float* __restrict__ b0p, const float* __restrict__ b1p,
              const float* __restrict__ b2p,
              float* __restrict__ out)
{
    extern __shared__ __align__(16) char smem[];
    const uint32_t sb = smem_u32(smem);

    const int t = threadIdx.x;
    const int warp = t >> 5, lane = t & 31;
    const int warpM = warp >> 2, warpN = warp & 3;
    const int z = blockIdx.z;
    const int blockM = blockIdx.y * 128;
    const int blockN = blockIdx.x * 128;

    const __nv_bfloat16* Whi = g_whi + (size_t)(wslot + z) * DM * DM;
    const __nv_bfloat16* Wlo = g_wlo + (size_t)(wslot + z) * DM * DM;
    const float* bias = (z == 0) ? b0p : ((z == 1) ? b1p : b2p);

    const int lr = t >> 2;             // 0..63 base row (2 iters -> 128)
    const int lsg = (t & 3) * 8;       // element offset in chunk

    float4 acc[4][4];
#pragma unroll
    for (int i = 0; i < 4; i++)
#pragma unroll
        for (int j = 0; j < 4; j++) acc[i][j] = make_float4(0.f, 0.f, 0.f, 0.f);

    // prologue: chunk 0 -> stage 0
    {
#pragma unroll
        for (int it = 0; it < 2; it++) {
            const int r = lr + it * 64;
            const uint32_t so = r * GRS + lsg * 2;
            cp16(sb + GA_HI + so, Ahi + (size_t)(blockM + r) * DM + lsg);
            cp16(sb + GA_LO + so, Alo + (size_t)(blockM + r) * DM + lsg);
            cp16(sb + GB_HI + so, Whi + (size_t)(blockN + r) * DM + lsg);
            cp16(sb + GB_LO + so, Wlo + (size_t)(blockN + r) * DM + lsg);
        }
        cp_commit();
    }

    for (int c = 0; c < 32; c++) {
        if (c + 1 < 32) {
            const uint32_t stg = sb + ((c + 1) & 1) * G_STG;
            const int kc = (c + 1) * 32;
#pragma unroll
            for (int it = 0; it < 2; it++) {
                const int r = lr + it * 64;
                const uint32_t so = r * GRS + lsg * 2;
                cp16(stg + GA_HI + so, Ahi + (size_t)(blockM + r) * DM + kc + lsg);
                cp16(stg + GA_LO + so, Alo + (size_t)(blockM + r) * DM + kc + lsg);
                cp16(stg + GB_HI + so, Whi + (size_t)(blockN + r) * DM + kc + lsg);
                cp16(stg + GB_LO + so, Wlo + (size_t)(blockN + r) * DM + kc + lsg);
            }
            cp_commit();
            cp_wait<1>();
        } else {
            cp_wait<0>();
        }
        __syncthreads();

        const uint32_t stg = sb + (c & 1) * G_STG;
#pragma unroll
        for (int ks = 0; ks < 2; ks++) {
            const uint32_t acol = (ks * 16 + (lane >> 4) * 8) * 2;
            const uint32_t bcol = (ks * 16 + ((lane >> 3) & 1) * 8) * 2;

            uint32_t a[4][4];
#pragma unroll
            for (int i = 0; i < 4; i++) {
                uint32_t ad = stg + GA_HI + (warpM * 64 + i * 16 + (lane & 15)) * GRS + acol;
                LDSM_X4(a[i][0], a[i][1], a[i][2], a[i][3], ad);
            }
            uint32_t bh[4][2], bl[4][2];
#pragma unroll
            for (int p = 0; p < 2; p++) {
                const uint32_t brow = (warpN * 32 + p * 16 + ((lane >> 4) * 8) + (lane & 7)) * GRS;
                uint32_t m0, m1, m2, m3;
                LDSM_X4(m0, m1, m2, m3, stg + GB_HI + brow + bcol);
                bh[2 * p][0] = m0; bh[2 * p][1] = m1; bh[2 * p + 1][0] = m2; bh[2 * p + 1][1] = m3;
                LDSM_X4(m0, m1, m2, m3, stg + GB_LO + brow + bcol);
                bl[2 * p][0] = m0; bl[2 * p][1] = m1; bl[2 * p + 1][0] = m2; bl[2 * p + 1][1] = m3;
            }
#pragma unroll
            for (int i = 0; i < 4; i++)
#pragma unroll
                for (int j = 0; j < 4; j++) {
                    mma_bf16(acc[i][j], a[i], bh[j][0], bh[j][1]);
                    mma_bf16(acc[i][j], a[i], bl[j][0], bl[j][1]);
                }
#pragma unroll
            for (int i = 0; i < 4; i++) {
                uint32_t ad = stg + GA_LO + (warpM * 64 + i * 16 + (lane & 15)) * GRS + acol;
                LDSM_X4(a[i][0], a[i][1], a[i][2], a[i][3], ad);
            }
#pragma unroll
            for (int i = 0; i < 4; i++)
#pragma unroll
                for (int j = 0; j < 4; j++)
                    mma_bf16(acc[i][j], a[i], bh[j][0], bh[j][1]);
        }
        __syncthreads();
    }

    // epilogue (q gets QSCALE * LOG2E so softmax runs in exp2 domain)
    const float sc = (MODE == 0 && z == 0) ? (QSCALE * LOG2E) : 1.f;
#pragma unroll
    for (int i = 0; i < 4; i++) {
#pragma unroll
        for (int j = 0; j < 4; j++) {
            const int row0 = blockM + warpM * 64 + i * 16 + (lane >> 2);
            const int row1 = row0 + 8;
            const int col = blockN + warpN * 32 + j * 8 + (lane & 3) * 2;
            const float bx = bias[col], by = bias[col + 1];
            const float vx = (acc[i][j].x + bx) * sc;
            const float vy = (acc[i][j].y + by) * sc;
            const float vz = (acc[i][j].z + bx) * sc;
            const float vw = (acc[i][j].w + by) * sc;
            if (MODE == 1) {
                *(float2*)(out + (size_t)row0 * DM + col) = make_float2(vx, vy);
                *(float2*)(out + (size_t)row1 * DM + col) = make_float2(vz, vw);
            } else {
                const int hh = col >> 6, d = col & 63;
                const size_t a0 = (size_t)hh * SQ * HS + (size_t)row0 * HS + d;
                const size_t a1 = (size_t)hh * SQ * HS + (size_t)row1 * HS + d;
                if (z < 2) {
                    __nv_bfloat16* harr = z ? g_khi : g_qhi;
                    __nv_bfloat16* larr = z ? g_klo : g_qlo;
                    unsigned l0, l1;
                    unsigned h0 = pack_hi2(vx, vy, l0);
                    unsigned h1 = pack_hi2(vz, vw, l1);
                    *(uint32_t*)(harr + a0) = h0;
                    *(uint32_t*)(larr + a0) = l0;
                    *(uint32_t*)(harr + a1) = h1;
                    *(uint32_t*)(larr + a1) = l1;
                } else {
                    *(uint32_t*)(g_vhi + a0) = pack_h2(vx, vy);
                    *(uint32_t*)(g_vhi + a1) = pack_h2(vz, vw);
                }
            }
        }
    }
}

// ============================================================================
// Flash attention, cp.async ring-3 K/V pipeline, exp2-domain softmax.
// Block: 128 q-rows x 1 head, 256 threads (8 warps).
// smem: Q staged at [0,36864) then region reused as 3 ring buffers of 27648.
// ============================================================================
#define GSTB 144
#define KVBUF 27648
#define OFF_KHI 0
#define OFF_KLO 9216
#define OFF_VHI 18432
#define ATTN_SMEM_TOT (3 * KVBUF)   // 82944

__global__ __launch_bounds__(256, 2)
void attn_mma()
{
    extern __shared__ __align__(16) char smem[];
    const uint32_t sb = smem_u32(smem);

    const int h  = blockIdx.y;
    const int qb = gridDim.x - 1 - blockIdx.x;   // heavy blocks first
    const int t = threadIdx.x;
    const int warp = t >> 5, lane = t & 31;

    const size_t hbase = (size_t)h * SQ * HS;

    // ---- stage Q tile (128 rows, hi|lo) at smem[0..36864) ----
#pragma unroll
    for (int it = 0; it < 4; it++) {
        const int idx = it * 256 + t;
        const int r = idx >> 3;
        const int c8 = (idx & 7) * 8;
        const size_t g = hbase + (size_t)(qb * 128 + r) * HS + c8;
        const uint32_t so = r * GSTB + c8 * 2;
        *(uint4*)(smem + so) = *(const uint4*)(g_qhi + g);
        *(uint4*)(smem + 18432 + so) = *(const uint4*)(g_qlo + g);
    }
    __syncthreads();

    // ---- preload Q fragments into registers ----
    uint32_t qh[4][4], ql[4][4];
#pragma unroll
    for (int ks = 0; ks < 4; ks++) {
        const uint32_t ro = (warp * 16 + (lane & 15)) * GSTB + (ks * 16 + (lane >> 4) * 8) * 2;
        LDSM_X4(qh[ks][0], qh[ks][1], qh[ks][2], qh[ks][3], sb + ro);
        LDSM_X4(ql[ks][0], ql[ks][1], ql[ks][2], ql[ks][3], sb + 18432 + ro);
    }
    __syncthreads();   // all warps done with Q smem before ring reuses it

    const int nkt = 2 * qb + 2;

    // ---- prologue: 3 commit groups (tiles 0..2, empty-padded) ----
#pragma unroll
    for (int i = 0; i < 3; i++) {
        if (i < nkt) {
            const uint32_t bufb = sb + i * KVBUF;
#pragma unroll
            for (int it = 0; it < 2; it++) {
                const int idx = it * 256 + t;
                const int r = idx >> 3;
                const int c8 = (idx & 7) * 8;
                const size_t g = hbase + (size_t)(i * 64 + r) * HS + c8;
                const uint32_t so = r * GSTB + c8 * 2;
                cp16(bufb + OFF_KHI + so, g_khi + g);
                cp16(bufb + OFF_KLO + so, g_klo + g);
                cp16(bufb + OFF_VHI + so, g_vhi + g);
            }
        }
        cp_commit();
    }

    float4 o[8];
#pragma unroll
    for (int f = 0; f < 8; f++) o[f] = make_float4(0.f, 0.f, 0.f, 0.f);
    float m0 = -1e30f, m1 = -1e30f, l0s = 0.f, l1s = 0.f;

    int buf = 0;
    for (int kt = 0; kt < nkt; kt++) {
        cp_wait<2>();
        __syncthreads();

        const uint32_t kvb = sb + buf * KVBUF;

        // ---- S = Q K^T (bf16 3-term) ----
        float4 s[8];
#pragma unroll
        for (int f = 0; f < 8; f++) s[f] = make_float4(0.f, 0.f, 0.f, 0.f);

#pragma unroll
        for (int ks = 0; ks < 4; ks++) {
            const uint32_t bcol = (ks * 16 + ((lane >> 3) & 1) * 8) * 2;
#pragma unroll
            for (int p = 0; p < 4; p++) {
                const uint32_t brow = (p * 16 + ((lane >> 4) * 8) + (lane & 7)) * GSTB;
                uint32_t h0, h1, h2, h3, l0, l1, l2, l3;
                LDSM_X4(h0, h1, h2, h3, kvb + OFF_KHI + brow + bcol);
                LDSM_X4(l0, l1, l2, l3, kvb + OFF_KLO + brow + bcol);
                mma_bf16(s[2 * p],     qh[ks], h0, h1);
                mma_bf16(s[2 * p],     qh[ks], l0, l1);
                mma_bf16(s[2 * p],     ql[ks], h0, h1);
                mma_bf16(s[2 * p + 1], qh[ks], h2, h3);
                mma_bf16(s[2 * p + 1], qh[ks], l2, l3);
                mma_bf16(s[2 * p + 1], ql[ks], h2, h3);
            }
        }

        // ---- causal mask (diagonal-straddling tiles only) ----
        if (kt * 64 + 63 > qb * 128 + warp * 16) {
            const int q0 = qb * 128 + warp * 16 + (lane >> 2);
            const int q1 = q0 + 8;
#pragma unroll
            for (int f = 0; f < 8; f++) {
                const int kc = kt * 64 + f * 8 + (lane & 3) * 2;
                if (kc > q0)     s[f].x = NEG;
                if (kc + 1 > q0) s[f].y = NEG;
                if (kc > q1)     s[f].z = NEG;
                if (kc + 1 > q1) s[f].w = NEG;
            }
        }

        // ---- online softmax (exp2 domain) ----
        float rmax0 = NEG, rmax1 = NEG;
#pragma unroll
        for (int f = 0; f < 8; f++) {
            rmax0 = fmaxf(rmax0, fmaxf(s[f].x, s[f].y));
            rmax1 = fmaxf(rmax1, fmaxf(s[f].z, s[f].w));
        }
        rmax0 = fmaxf(rmax0, __shfl_xor_sync(0xffffffffu, rmax0, 1));
        rmax0 = fmaxf(rmax0, __shfl_xor_sync(0xffffffffu, rmax0, 2));
        rmax1 = fmaxf(rmax1, __shfl_xor_sync(0xffffffffu, rmax1, 1));
        rmax1 = fmaxf(rmax1, __shfl_xor_sync(0xffffffffu, rmax1, 2));

        const float mn0 = fmaxf(m0, rmax0);
        const float mn1 = fmaxf(m1, rmax1);
        const float c0 = exp2f(m0 - mn0);
        const float c1 = exp2f(m1 - mn1);

        float rs0 = 0.f, rs1 = 0.f;
#pragma unroll
        for (int f = 0; f < 8; f++) {
            s[f].x = exp2f(s[f].x - mn0);
            s[f].y = exp2f(s[f].y - mn0);
            s[f].z = exp2f(s[f].z - mn1);
            s[f].w = exp2f(s[f].w - mn1);
            rs0 += s[f].x + s[f].y;
            rs1 += s[f].z + s[f].w;
        }
        rs0 += __shfl_xor_sync(0xffffffffu, rs0, 1);
        rs0 += __shfl_xor_sync(0xffffffffu, rs0, 2);
        rs1 += __shfl_xor_sync(0xffffffffu, rs1, 1);
        rs1 += __shfl_xor_sync(0xffffffffu, rs1, 2);

        l0s = l0s * c0 + rs0;
        l1s = l1s * c1 + rs1;
        m0 = mn0; m1 = mn1;
#pragma unroll
        for (int f = 0; f < 8; f++) {
            o[f].x *= c0; o[f].y *= c0; o[f].z *= c1; o[f].w *= c1;
        }

        // ---- O += P V ----
#pragma unroll
        for (int ks = 0; ks < 4; ks++) {
            uint32_t ap[4];
            ap[0] = pack_h2(s[2 * ks].x,     s[2 * ks].y);
            ap[1] = pack_h2(s[2 * ks].z,     s[2 * ks].w);
            ap[2] = pack_h2(s[2 * ks + 1].x, s[2 * ks + 1].y);
            ap[3] = pack_h2(s[2 * ks + 1].z, s[2 * ks + 1].w);

            const uint32_t vrow = (ks * 16 + (lane & 7) + ((lane >> 3) & 1) * 8) * GSTB;
#pragma unroll
            for (int g = 0; g < 4; g++) {
                const uint32_t vcol = (g * 16 + (lane >> 4) * 8) * 2;
                uint32_t v0, v1, v2, v3;
                LDSM_X4_T(v0, v1, v2, v3, kvb + OFF_VHI + vrow + vcol);
                mma_f16(o[2 * g],     ap, v0, v1);
                mma_f16(o[2 * g + 1], ap, v2, v3);
            }
        }

        __syncthreads();   // all warps done with buf before refill
        if (kt + 3 < nkt) {
            const uint32_t bufb = sb + buf * KVBUF;
#pragma unroll
            for (int it = 0; it < 2; it++) {
                const int idx = it * 256 + t;
                const int r = idx >> 3;
                const int c8 = (idx & 7) * 8;
                const size_t g = hbase + (size_t)((kt + 3) * 64 + r) * HS + c8;
                const uint32_t so = r * GSTB + c8 * 2;
                cp16(bufb + OFF_KHI + so, g_khi + g);
                cp16(bufb + OFF_KLO + so, g_klo + g);
                cp16(bufb + OFF_VHI + so, g_vhi + g);
            }
        }
        cp_commit();
        buf = (buf + 1) % 3;
    }

    // ---- normalize + write split bf16 hi/lo (feeds O projection) ----
    const float inv0 = 1.f / l0s;
    const float inv1 = 1.f / l1s;
    const int r0 = qb * 128 + warp * 16 + (lane >> 2);
    const int r1 = r0 + 8;
#pragma unroll
    for (int f = 0; f < 8; f++) {
        const int col = h * HS + f * 8 + (lane & 3) * 2;
        unsigned l0p, l1p;
        unsigned h0p = pack_hi2(o[f].x * inv0, o[f].y * inv0, l0p);
        unsigned h1p = pack_hi2(o[f].z * inv1, o[f].w * inv1, l1p);
        *(uint32_t*)(g_xhi + (size_t)r0 * DM + col) = h0p;
        *(uint32_t*)(g_xlo + (size_t)r0 * DM + col) = l0p;
        *(uint32_t*)(g_xhi + (size_t)r1 * DM + col) = h1p;
        *(uint32_t*)(g_xlo + (size_t)r1 * DM + col) = l1p;
    }
}

// ============================================================================
// launch
// ============================================================================
extern "C" void kernel_launch(void* const* d_in, const int* in_sizes, int n_in,
                              void* d_out, int out_size)
{
    (void)in_sizes; (void)n_in; (void)out_size;
    const float* x  = (const float*)d_in[0];
    const float* wq = (const float*)d_in[1];
    const float* bq = (const float*)d_in[2];
    const float* wk = (const float*)d_in[3];
    const float* bk = (const float*)d_in[4];
    const float* wv = (const float*)d_in[5];
    const float* bv = (const float*)d_in[6];
    const float* wo = (const float*)d_in[7];
    const float* bo = (const float*)d_in[8];
    float* out = (float*)d_out;

    __nv_bfloat16 *xhi, *xlo;
    cudaGetSymbolAddress((void**)&xhi, g_xhi);
    cudaGetSymbolAddress((void**)&xlo, g_xlo);

    const int GEMM_SMEM = 2 * G_STG;          // 81920
    cudaFuncSetAttribute(gemm_mma<0>,
                         cudaFuncAttributeMaxDynamicSharedMemorySize, GEMM_SMEM);
    cudaFuncSetAttribute(gemm_mma<1>,
                         cudaFuncAttributeMaxDynamicSharedMemorySize, GEMM_SMEM);
    cudaFuncSetAttribute(attn_mma,
                         cudaFuncAttributeMaxDynamicSharedMemorySize, ATTN_SMEM_TOT);

    split5_kernel<<<dim3(512, 1, 5), 256>>>((const float4*)wq, (const float4*)wk,
                                            (const float4*)wv, (const float4*)wo,
                                            (const float4*)x);

    gemm_mma<0><<<dim3(DM / 128, SQ / 128, 3), 256, GEMM_SMEM>>>(
        xhi, xlo, 0, bq, bk, bv, nullptr);

    attn_mma<<<dim3(SQ / 128, NH), 256, ATTN_SMEM_TOT>>>();

    gemm_mma<1><<<dim3(DM / 128, SQ / 128, 1), 256, GEMM_SMEM>>>(
        xhi, xlo, 3, bo, bo, bo, out);
}

// round 8
// speedup vs baseline: 1.1460x; 1.1460x over previous
#include <cuda_runtime.h>
#include <cuda_bf16.h>
#include <cuda_fp16.h>
#include <cstdint>

#define SQ 4096
#define DM 1024
#define NH 16
#define HS 64
#define QSCALE 0.125f
#define LOG2E 1.4426950408889634f
#define NEG -1e9f

// -------- scratch (no allocations allowed) --------
__device__ __align__(16) __nv_bfloat16 g_xhi[SQ * DM];
__device__ __align__(16) __nv_bfloat16 g_xlo[SQ * DM];
__device__ __align__(16) __nv_bfloat16 g_whi[4 * DM * DM];
__device__ __align__(16) __nv_bfloat16 g_wlo[4 * DM * DM];
__device__ __align__(16) __nv_bfloat16 g_qhi[NH * SQ * HS];
__device__ __align__(16) __nv_bfloat16 g_qlo[NH * SQ * HS];
__device__ __align__(16) __nv_bfloat16 g_khi[NH * SQ * HS];
__device__ __align__(16) __nv_bfloat16 g_klo[NH * SQ * HS];
__device__ __align__(16) __half       g_vhi[NH * SQ * HS];

// ============================================================================
// helpers
// ============================================================================
__device__ __forceinline__ uint32_t smem_u32(const void* p) {
    uint32_t a;
    asm("{ .reg .u64 t; cvta.to.shared.u64 t, %1; cvt.u32.u64 %0, t; }" : "=r"(a) : "l"(p));
    return a;
}

#define LDSM_X4(r0, r1, r2, r3, addr) \
    asm volatile("ldmatrix.sync.aligned.m8n8.x4.shared.b16 {%0,%1,%2,%3}, [%4];" \
                 : "=r"(r0), "=r"(r1), "=r"(r2), "=r"(r3) : "r"(addr))

#define LDSM_X4_T(r0, r1, r2, r3, addr) \
    asm volatile("ldmatrix.sync.aligned.m8n8.x4.trans.shared.b16 {%0,%1,%2,%3}, [%4];" \
                 : "=r"(r0), "=r"(r1), "=r"(r2), "=r"(r3) : "r"(addr))

__device__ __forceinline__ void mma_bf16(float4& d, const uint32_t* a, uint32_t b0, uint32_t b1) {
    asm volatile("mma.sync.aligned.m16n8k16.row.col.f32.bf16.bf16.f32 "
                 "{%0,%1,%2,%3}, {%4,%5,%6,%7}, {%8,%9}, {%0,%1,%2,%3};"
                 : "+f"(d.x), "+f"(d.y), "+f"(d.z), "+f"(d.w)
                 : "r"(a[0]), "r"(a[1]), "r"(a[2]), "r"(a[3]), "r"(b0), "r"(b1));
}

__device__ __forceinline__ void mma_f16(float4& d, const uint32_t* a, uint32_t b0, uint32_t b1) {
    asm volatile("mma.sync.aligned.m16n8k16.row.col.f32.f16.f16.f32 "
                 "{%0,%1,%2,%3}, {%4,%5,%6,%7}, {%8,%9}, {%0,%1,%2,%3};"
                 : "+f"(d.x), "+f"(d.y), "+f"(d.z), "+f"(d.w)
                 : "r"(a[0]), "r"(a[1]), "r"(a[2]), "r"(a[3]), "r"(b0), "r"(b1));
}

__device__ __forceinline__ void cp16(uint32_t s, const void* g) {
    asm volatile("cp.async.cg.shared.global [%0], [%1], 16;" :: "r"(s), "l"(g));
}
__device__ __forceinline__ void cp_commit() {
    asm volatile("cp.async.commit_group;" ::: "memory");
}
template <int N>
__device__ __forceinline__ void cp_wait() {
    asm volatile("cp.async.wait_group %0;" :: "n"(N) : "memory");
}

__device__ __forceinline__ unsigned pack_bf2(float a, float b) {
    __nv_bfloat16 ha = __float2bfloat16_rn(a);
    __nv_bfloat16 hb = __float2bfloat16_rn(b);
    return (unsigned)__bfloat16_as_ushort(ha) | ((unsigned)__bfloat16_as_ushort(hb) << 16);
}
__device__ __forceinline__ unsigned pack_hi2(float a, float b, unsigned& lo) {
    __nv_bfloat16 ha = __float2bfloat16_rn(a);
    __nv_bfloat16 hb = __float2bfloat16_rn(b);
    float ra = a - __bfloat162float(ha);
    float rb = b - __bfloat162float(hb);
    lo = pack_bf2(ra, rb);
    return (unsigned)__bfloat16_as_ushort(ha) | ((unsigned)__bfloat16_as_ushort(hb) << 16);
}
__device__ __forceinline__ unsigned pack_h2(float a, float b) {
    __half2 h = __floats2half2_rn(a, b);
    return *(unsigned*)&h;
}

// ============================================================================
// fused split: z<4 -> weights, z==4 -> x
// ============================================================================
__global__ __launch_bounds__(256)
void split5_kernel(const float4* __restrict__ w0, const float4* __restrict__ w1,
                   const float4* __restrict__ w2, const float4* __restrict__ w3,
                   const float4* __restrict__ x)
{
    const int z = blockIdx.z;
    const float4* src;
    uint2 *hi, *lo;
    int n4;
    if (z < 4) {
        src = (z == 0) ? w0 : (z == 1) ? w1 : (z == 2) ? w2 : w3;
        hi = (uint2*)(g_whi + (size_t)z * DM * DM);
        lo = (uint2*)(g_wlo + (size_t)z * DM * DM);
        n4 = DM * DM / 4;
    } else {
        src = x;
        hi = (uint2*)g_xhi;
        lo = (uint2*)g_xlo;
        n4 = SQ * DM / 4;
    }
    for (int i = blockIdx.x * blockDim.x + threadIdx.x; i < n4;
         i += gridDim.x * blockDim.x) {
        float4 v = src[i];
        unsigned l0, l1;
        unsigned h0 = pack_hi2(v.x, v.y, l0);
        unsigned h1 = pack_hi2(v.z, v.w, l1);
        hi[i] = make_uint2(h0, h1);
        lo[i] = make_uint2(l0, l1);
    }
}

// ============================================================================
// GEMM via mma.sync, bf16 hi/lo 3-term. 128x128 tile, K-chunk 32,
// ring-3 cp.async pipeline, XOR-swizzled smem (64B rows, no pad),
// ONE __syncthreads per chunk.
// ============================================================================
#define G_STG 32768            // 4 arrays * 128 rows * 64 B
#define GA_HI 0
#define GA_LO 8192
#define GB_HI 16384
#define GB_LO 24576

__device__ __forceinline__ uint32_t gswz(int row, int chunk) {
    return (uint32_t)(row * 64 + ((chunk ^ ((row >> 1) & 3)) << 4));
}

template <int MODE>
__global__ __launch_bounds__(256, 2)
void gemm_mma(const __nv_bfloat16* __restrict__ Ahi,
              const __nv_bfloat16* __restrict__ Alo,
              int wslot,
              const float* __restrict__ b0p, const float* __restrict__ b1p,
              const float* __restrict__ b2p,
              float* __restrict__ out)
{
    extern __shared__ __align__(16) char smem[];
    const uint32_t sb = smem_u32(smem);

    const int t = threadIdx.x;
    const int warp = t >> 5, lane = t & 31;
    const int warpM = warp >> 2, warpN = warp & 3;
    const int z = blockIdx.z;
    const int blockM = blockIdx.y * 128;
    const int blockN = blockIdx.x * 128;

    const __nv_bfloat16* Whi = g_whi + (size_t)(wslot + z) * DM * DM;
    const __nv_bfloat16* Wlo = g_wlo + (size_t)(wslot + z) * DM * DM;
    const float* bias = (z == 0) ? b0p : ((z == 1) ? b1p : b2p);

    const int lr = t >> 2;             // 0..63 base row (2 iters -> 128)
    const int lch = t & 3;             // 16B chunk within 64B row

    float4 acc[4][4];
#pragma unroll
    for (int i = 0; i < 4; i++)
#pragma unroll
        for (int j = 0; j < 4; j++) acc[i][j] = make_float4(0.f, 0.f, 0.f, 0.f);

    // prologue: chunks 0,1 -> stages 0,1 (2 commit groups)
#pragma unroll
    for (int pc = 0; pc < 2; pc++) {
        const uint32_t stg = sb + pc * G_STG;
        const int kc = pc * 32 + lch * 8;
#pragma unroll
        for (int it = 0; it < 2; it++) {
            const int r = lr + it * 64;
            const uint32_t so = gswz(r, lch);
            cp16(stg + GA_HI + so, Ahi + (size_t)(blockM + r) * DM + kc);
            cp16(stg + GA_LO + so, Alo + (size_t)(blockM + r) * DM + kc);
            cp16(stg + GB_HI + so, Whi + (size_t)(blockN + r) * DM + kc);
            cp16(stg + GB_LO + so, Wlo + (size_t)(blockN + r) * DM + kc);
        }
        cp_commit();
    }

    for (int c = 0; c < 32; c++) {
        cp_wait<1>();
        __syncthreads();

        const uint32_t stg = sb + (c % 3) * G_STG;
#pragma unroll
        for (int ks = 0; ks < 2; ks++) {
            const int chA = 2 * ks + (lane >> 4);
            const int chB = 2 * ks + ((lane >> 3) & 1);

            uint32_t a[4][4];
#pragma unroll
            for (int i = 0; i < 4; i++) {
                const int arow = warpM * 64 + i * 16 + (lane & 15);
                LDSM_X4(a[i][0], a[i][1], a[i][2], a[i][3],
                        stg + GA_HI + gswz(arow, chA));
            }
            uint32_t bh[4][2], bl[4][2];
#pragma unroll
            for (int p = 0; p < 2; p++) {
                const int brow = warpN * 32 + p * 16 + ((lane >> 4) * 8) + (lane & 7);
                uint32_t m0, m1, m2, m3;
                LDSM_X4(m0, m1, m2, m3, stg + GB_HI + gswz(brow, chB));
                bh[2 * p][0] = m0; bh[2 * p][1] = m1; bh[2 * p + 1][0] = m2; bh[2 * p + 1][1] = m3;
                LDSM_X4(m0, m1, m2, m3, stg + GB_LO + gswz(brow, chB));
                bl[2 * p][0] = m0; bl[2 * p][1] = m1; bl[2 * p + 1][0] = m2; bl[2 * p + 1][1] = m3;
            }
#pragma unroll
            for (int i = 0; i < 4; i++)
#pragma unroll
                for (int j = 0; j < 4; j++) {
                    mma_bf16(acc[i][j], a[i], bh[j][0], bh[j][1]);
                    mma_bf16(acc[i][j], a[i], bl[j][0], bl[j][1]);
                }
#pragma unroll
            for (int i = 0; i < 4; i++) {
                const int arow = warpM * 64 + i * 16 + (lane & 15);
                LDSM_X4(a[i][0], a[i][1], a[i][2], a[i][3],
                        stg + GA_LO + gswz(arow, chA));
            }
#pragma unroll
            for (int i = 0; i < 4; i++)
#pragma unroll
                for (int j = 0; j < 4; j++)
                    mma_bf16(acc[i][j], a[i], bh[j][0], bh[j][1]);
        }

        // issue chunk c+2 into stage (c+2)%3 (last read at iter c-1; top sync fences)
        if (c + 2 < 32) {
            const uint32_t stg2 = sb + ((c + 2) % 3) * G_STG;
            const int kc = (c + 2) * 32 + lch * 8;
#pragma unroll
            for (int it = 0; it < 2; it++) {
                const int r = lr + it * 64;
                const uint32_t so = gswz(r, lch);
                cp16(stg2 + GA_HI + so, Ahi + (size_t)(blockM + r) * DM + kc);
                cp16(stg2 + GA_LO + so, Alo + (size_t)(blockM + r) * DM + kc);
                cp16(stg2 + GB_HI + so, Whi + (size_t)(blockN + r) * DM + kc);
                cp16(stg2 + GB_LO + so, Wlo + (size_t)(blockN + r) * DM + kc);
            }
        }
        cp_commit();   // always commit (keeps wait<1> counting invariant)
    }

    // epilogue (q scaled into exp2 domain)
    const float sc = (MODE == 0 && z == 0) ? (QSCALE * LOG2E) : 1.f;
#pragma unroll
    for (int i = 0; i < 4; i++) {
#pragma unroll
        for (int j = 0; j < 4; j++) {
            const int row0 = blockM + warpM * 64 + i * 16 + (lane >> 2);
            const int row1 = row0 + 8;
            const int col = blockN + warpN * 32 + j * 8 + (lane & 3) * 2;
            const float bx = bias[col], by = bias[col + 1];
            const float vx = (acc[i][j].x + bx) * sc;
            const float vy = (acc[i][j].y + by) * sc;
            const float vz = (acc[i][j].z + bx) * sc;
            const float vw = (acc[i][j].w + by) * sc;
            if (MODE == 1) {
                *(float2*)(out + (size_t)row0 * DM + col) = make_float2(vx, vy);
                *(float2*)(out + (size_t)row1 * DM + col) = make_float2(vz, vw);
            } else {
                const int hh = col >> 6, d = col & 63;
                const size_t a0 = (size_t)hh * SQ * HS + (size_t)row0 * HS + d;
                const size_t a1 = (size_t)hh * SQ * HS + (size_t)row1 * HS + d;
                if (z < 2) {
                    __nv_bfloat16* harr = z ? g_khi : g_qhi;
                    __nv_bfloat16* larr = z ? g_klo : g_qlo;
                    unsigned l0, l1;
                    unsigned h0 = pack_hi2(vx, vy, l0);
                    unsigned h1 = pack_hi2(vz, vw, l1);
                    *(uint32_t*)(harr + a0) = h0;
                    *(uint32_t*)(larr + a0) = l0;
                    *(uint32_t*)(harr + a1) = h1;
                    *(uint32_t*)(larr + a1) = l1;
                } else {
                    *(uint32_t*)(g_vhi + a0) = pack_h2(vx, vy);
                    *(uint32_t*)(g_vhi + a1) = pack_h2(vz, vw);
                }
            }
        }
    }
}

// ============================================================================
// Flash attention, ring-3 cp.async, ONE sync per k-tile, exp2 softmax.
// Block: 128 q-rows x 1 head, 256 threads (8 warps).
// ============================================================================
#define GSTB 144
#define KVBUF 27648
#define OFF_KHI 0
#define OFF_KLO 9216
#define OFF_VHI 18432
#define ATTN_SMEM_TOT (3 * KVBUF)   // 82944

__global__ __launch_bounds__(256, 2)
void attn_mma()
{
    extern __shared__ __align__(16) char smem[];
    const uint32_t sb = smem_u32(smem);

    const int h  = blockIdx.y;
    const int qb = gridDim.x - 1 - blockIdx.x;   // heavy blocks first
    const int t = threadIdx.x;
    const int warp = t >> 5, lane = t & 31;

    const size_t hbase = (size_t)h * SQ * HS;

    // ---- stage Q tile (128 rows, hi|lo) in ring region (reused after) ----
#pragma unroll
    for (int it = 0; it < 4; it++) {
        const int idx = it * 256 + t;
        const int r = idx >> 3;
        const int c8 = (idx & 7) * 8;
        const size_t g = hbase + (size_t)(qb * 128 + r) * HS + c8;
        const uint32_t so = r * GSTB + c8 * 2;
        *(uint4*)(smem + so) = *(const uint4*)(g_qhi + g);
        *(uint4*)(smem + 18432 + so) = *(const uint4*)(g_qlo + g);
    }
    __syncthreads();

    uint32_t qh[4][4], ql[4][4];
#pragma unroll
    for (int ks = 0; ks < 4; ks++) {
        const uint32_t ro = (warp * 16 + (lane & 15)) * GSTB + (ks * 16 + (lane >> 4) * 8) * 2;
        LDSM_X4(qh[ks][0], qh[ks][1], qh[ks][2], qh[ks][3], sb + ro);
        LDSM_X4(ql[ks][0], ql[ks][1], ql[ks][2], ql[ks][3], sb + 18432 + ro);
    }
    __syncthreads();   // Q consumed before ring reuse

    const int nkt = 2 * qb + 2;

    // ---- prologue: tiles 0,1 -> buffers 0,1 (2 commits) ----
#pragma unroll
    for (int i = 0; i < 2; i++) {
        const uint32_t bufb = sb + i * KVBUF;
#pragma unroll
        for (int it = 0; it < 2; it++) {
            const int idx = it * 256 + t;
            const int r = idx >> 3;
            const int c8 = (idx & 7) * 8;
            const size_t g = hbase + (size_t)(i * 64 + r) * HS + c8;
            const uint32_t so = r * GSTB + c8 * 2;
            cp16(bufb + OFF_KHI + so, g_khi + g);
            cp16(bufb + OFF_KLO + so, g_klo + g);
            cp16(bufb + OFF_VHI + so, g_vhi + g);
        }
        cp_commit();
    }

    float4 o[8];
#pragma unroll
    for (int f = 0; f < 8; f++) o[f] = make_float4(0.f, 0.f, 0.f, 0.f);
    float m0 = -1e30f, m1 = -1e30f, l0s = 0.f, l1s = 0.f;

    for (int kt = 0; kt < nkt; kt++) {
        cp_wait<1>();
        __syncthreads();

        const uint32_t kvb = sb + (kt % 3) * KVBUF;

        // ---- S = Q K^T (bf16 3-term) ----
        float4 s[8];
#pragma unroll
        for (int f = 0; f < 8; f++) s[f] = make_float4(0.f, 0.f, 0.f, 0.f);

#pragma unroll
        for (int ks = 0; ks < 4; ks++) {
            const uint32_t bcol = (ks * 16 + ((lane >> 3) & 1) * 8) * 2;
#pragma unroll
            for (int p = 0; p < 4; p++) {
                const uint32_t brow = (p * 16 + ((lane >> 4) * 8) + (lane & 7)) * GSTB;
                uint32_t h0, h1, h2, h3, l0, l1, l2, l3;
                LDSM_X4(h0, h1, h2, h3, kvb + OFF_KHI + brow + bcol);
                LDSM_X4(l0, l1, l2, l3, kvb + OFF_KLO + brow + bcol);
                mma_bf16(s[2 * p],     qh[ks], h0, h1);
                mma_bf16(s[2 * p],     qh[ks], l0, l1);
                mma_bf16(s[2 * p],     ql[ks], h0, h1);
                mma_bf16(s[2 * p + 1], qh[ks], h2, h3);
                mma_bf16(s[2 * p + 1], qh[ks], l2, l3);
                mma_bf16(s[2 * p + 1], ql[ks], h2, h3);
            }
        }

        // ---- causal mask (diagonal-straddling tiles only) ----
        if (kt * 64 + 63 > qb * 128 + warp * 16) {
            const int q0 = qb * 128 + warp * 16 + (lane >> 2);
            const int q1 = q0 + 8;
#pragma unroll
            for (int f = 0; f < 8; f++) {
                const int kc = kt * 64 + f * 8 + (lane & 3) * 2;
                if (kc > q0)     s[f].x = NEG;
                if (kc + 1 > q0) s[f].y = NEG;
                if (kc > q1)     s[f].z = NEG;
                if (kc + 1 > q1) s[f].w = NEG;
            }
        }

        // ---- online softmax (exp2 domain) ----
        float rmax0 = NEG, rmax1 = NEG;
#pragma unroll
        for (int f = 0; f < 8; f++) {
            rmax0 = fmaxf(rmax0, fmaxf(s[f].x, s[f].y));
            rmax1 = fmaxf(rmax1, fmaxf(s[f].z, s[f].w));
        }
        rmax0 = fmaxf(rmax0, __shfl_xor_sync(0xffffffffu, rmax0, 1));
        rmax0 = fmaxf(rmax0, __shfl_xor_sync(0xffffffffu, rmax0, 2));
        rmax1 = fmaxf(rmax1, __shfl_xor_sync(0xffffffffu, rmax1, 1));
        rmax1 = fmaxf(rmax1, __shfl_xor_sync(0xffffffffu, rmax1, 2));

        const float mn0 = fmaxf(m0, rmax0);
        const float mn1 = fmaxf(m1, rmax1);
        const float c0 = exp2f(m0 - mn0);
        const float c1 = exp2f(m1 - mn1);

        float rs0 = 0.f, rs1 = 0.f;
#pragma unroll
        for (int f = 0; f < 8; f++) {
            s[f].x = exp2f(s[f].x - mn0);
            s[f].y = exp2f(s[f].y - mn0);
            s[f].z = exp2f(s[f].z - mn1);
            s[f].w = exp2f(s[f].w - mn1);
            rs0 += s[f].x + s[f].y;
            rs1 += s[f].z + s[f].w;
        }
        rs0 += __shfl_xor_sync(0xffffffffu, rs0, 1);
        rs0 += __shfl_xor_sync(0xffffffffu, rs0, 2);
        rs1 += __shfl_xor_sync(0xffffffffu, rs1, 1);
        rs1 += __shfl_xor_sync(0xffffffffu, rs1, 2);

        l0s = l0s * c0 + rs0;
        l1s = l1s * c1 + rs1;
        m0 = mn0; m1 = mn1;
#pragma unroll
        for (int f = 0; f < 8; f++) {
            o[f].x *= c0; o[f].y *= c0; o[f].z *= c1; o[f].w *= c1;
        }

        // ---- O += P V ----
#pragma unroll
        for (int ks = 0; ks < 4; ks++) {
            uint32_t ap[4];
            ap[0] = pack_h2(s[2 * ks].x,     s[2 * ks].y);
            ap[1] = pack_h2(s[2 * ks].z,     s[2 * ks].w);
            ap[2] = pack_h2(s[2 * ks + 1].x, s[2 * ks + 1].y);
            ap[3] = pack_h2(s[2 * ks + 1].z, s[2 * ks + 1].w);

            const uint32_t vrow = (ks * 16 + (lane & 7) + ((lane >> 3) & 1) * 8) * GSTB;
#pragma unroll
            for (int g = 0; g < 4; g++) {
                const uint32_t vcol = (g * 16 + (lane >> 4) * 8) * 2;
                uint32_t v0, v1, v2, v3;
                LDSM_X4_T(v0, v1, v2, v3, kvb + OFF_VHI + vrow + vcol);
                mma_f16(o[2 * g],     ap, v0, v1);
                mma_f16(o[2 * g + 1], ap, v2, v3);
            }
        }

        // ---- issue tile kt+2 into buffer (kt+2)%3 (read at kt-1; top sync fences) ----
        if (kt + 2 < nkt) {
            const uint32_t bufb = sb + ((kt + 2) % 3) * KVBUF;
#pragma unroll
            for (int it = 0; it < 2; it++) {
                const int idx = it * 256 + t;
                const int r = idx >> 3;
                const int c8 = (idx & 7) * 8;
                const size_t g = hbase + (size_t)((kt + 2) * 64 + r) * HS + c8;
                const uint32_t so = r * GSTB + c8 * 2;
                cp16(bufb + OFF_KHI + so, g_khi + g);
                cp16(bufb + OFF_KLO + so, g_klo + g);
                cp16(bufb + OFF_VHI + so, g_vhi + g);
            }
        }
        cp_commit();
    }

    // ---- normalize + write split bf16 hi/lo (feeds O projection) ----
    const float inv0 = 1.f / l0s;
    const float inv1 = 1.f / l1s;
    const int r0 = qb * 128 + warp * 16 + (lane >> 2);
    const int r1 = r0 + 8;
#pragma unroll
    for (int f = 0; f < 8; f++) {
        const int col = h * HS + f * 8 + (lane & 3) * 2;
        unsigned l0p, l1p;
        unsigned h0p = pack_hi2(o[f].x * inv0, o[f].y * inv0, l0p);
        unsigned h1p = pack_hi2(o[f].z * inv1, o[f].w * inv1, l1p);
        *(uint32_t*)(g_xhi + (size_t)r0 * DM + col) = h0p;
        *(uint32_t*)(g_xlo + (size_t)r0 * DM + col) = l0p;
        *(uint32_t*)(g_xhi + (size_t)r1 * DM + col) = h1p;
        *(uint32_t*)(g_xlo + (size_t)r1 * DM + col) = l1p;
    }
}

// ============================================================================
// launch
// ============================================================================
extern "C" void kernel_launch(void* const* d_in, const int* in_sizes, int n_in,
                              void* d_out, int out_size)
{
    (void)in_sizes; (void)n_in; (void)out_size;
    const float* x  = (const float*)d_in[0];
    const float* wq = (const float*)d_in[1];
    const float* bq = (const float*)d_in[2];
    const float* wk = (const float*)d_in[3];
    const float* bk = (const float*)d_in[4];
    const float* wv = (const float*)d_in[5];
    const float* bv = (const float*)d_in[6];
    const float* wo = (const float*)d_in[7];
    const float* bo = (const float*)d_in[8];
    float* out = (float*)d_out;

    __nv_bfloat16 *xhi, *xlo;
    cudaGetSymbolAddress((void**)&xhi, g_xhi);
    cudaGetSymbolAddress((void**)&xlo, g_xlo);

    const int GEMM_SMEM = 3 * G_STG;          // 98304
    cudaFuncSetAttribute(gemm_mma<0>,
                         cudaFuncAttributeMaxDynamicSharedMemorySize, GEMM_SMEM);
    cudaFuncSetAttribute(gemm_mma<1>,
                         cudaFuncAttributeMaxDynamicSharedMemorySize, GEMM_SMEM);
    cudaFuncSetAttribute(attn_mma,
                         cudaFuncAttributeMaxDynamicSharedMemorySize, ATTN_SMEM_TOT);

    split5_kernel<<<dim3(512, 1, 5), 256>>>((const float4*)wq, (const float4*)wk,
                                            (const float4*)wv, (const float4*)wo,
                                            (const float4*)x);

    gemm_mma<0><<<dim3(DM / 128, SQ / 128, 3), 256, GEMM_SMEM>>>(
        xhi, xlo, 0, bq, bk, bv, nullptr);

    attn_mma<<<dim3(SQ / 128, NH), 256, ATTN_SMEM_TOT>>>();

    gemm_mma<1><<<dim3(DM / 128, SQ / 128, 1), 256, GEMM_SMEM>>>(
        xhi, xlo, 3, bo, bo, bo, out);
}